// round 11
// baseline (speedup 1.0000x reference)
#include <cuda_runtime.h>

// MixEHR_Seed: B=64, V=10000, K=64 — GEMM-factorized formulation.
// out: temp_exp_m_batch [64,64], temp_exp_n [V,K], temp_exp_s [V,K], gamma_sr_sum [K], exp_q_z [1]

#define KD     64
#define BD     64
#define VD     10000
#define VCH    32
#define NCH    313            // ceil(VD/VCH)
#define NSLICE 32
#define ETA_F  0.1f
#define BETA_F 0.05f
#define MU_F   0.05f
#define MINI_F 1e-6f

#define OFF_N   4096
#define OFF_S   644096
#define OFF_GSR 1284096
#define OFF_QZ  1284160

__device__ float  g_colS[KD];
__device__ float  g_colES[KD];
__device__ float  g_colEN[KD];
__device__ float  g_invN[KD];
__device__ float  g_invS[KD];
__device__ float2 g_TL[BD * KD];           // (theta, theta*log theta)
__device__ float  g_P32[NSLICE * BD * KD]; // W@crr partials (512 KB)
__device__ float  g_Mseed[BD * KD];        // seed-row gamma*cnt accumulation

__device__ __forceinline__ float warp_sum(float x) {
    #pragma unroll
    for (int o = 16; o; o >>= 1)
        x += __shfl_xor_sync(0xffffffffu, x, o);
    return x;
}

// ln(x) for positive normal x, FMA-pipe only (no MUFU). |err| < ~2e-6.
__device__ __forceinline__ float fast_log(float x) {
    int ix = __float_as_int(x);
    int e  = (ix - 0x3f330000) >> 23;                 // m in [~0.699, ~1.398)
    float m = __int_as_float(ix - (e << 23));
    float f = m - 1.0f;
    float p = 0.09090909f;
    p = fmaf(p, f, -0.1f);
    p = fmaf(p, f,  0.11111111f);
    p = fmaf(p, f, -0.125f);
    p = fmaf(p, f,  0.14285714f);
    p = fmaf(p, f, -0.16666667f);
    p = fmaf(p, f,  0.2f);
    p = fmaf(p, f, -0.25f);
    p = fmaf(p, f,  0.33333333f);
    p = fmaf(p, f, -0.5f);
    p = fmaf(p, f,  1.0f);
    return fmaf((float)e, 0.69314718f, p * f);
}

__global__ void zero_kernel(float* out) {
    int i = blockIdx.x * blockDim.x + threadIdx.x;    // 128*256 = 32768
    reinterpret_cast<float4*>(g_P32)[i] = make_float4(0.f, 0.f, 0.f, 0.f);
    if (i < 1024) reinterpret_cast<float4*>(g_Mseed)[i] = make_float4(0.f, 0.f, 0.f, 0.f);
    if (i < KD) {
        out[OFF_GSR + i] = 0.0f;
        g_colS[i] = 0.0f; g_colES[i] = 0.0f; g_colEN[i] = 0.0f;
    }
    if (i == 0) out[OFF_QZ] = 0.0f;
}

__global__ void colsum_kernel(const float* __restrict__ seeds,
                              const float* __restrict__ exp_s,
                              const float* __restrict__ exp_n) {
    int tid = blockIdx.x * blockDim.x + threadIdx.x;
    int stride = gridDim.x * blockDim.x;
    float a = 0.0f, b = 0.0f, c = 0.0f;
    for (int i = tid; i < VD * KD; i += stride) {
        a += seeds[i]; b += exp_s[i]; c += exp_n[i];
    }
    int k = tid & (KD - 1);
    atomicAdd(&g_colS[k], a);
    atomicAdd(&g_colES[k], b);
    atomicAdd(&g_colEN[k], c);
}

__global__ void prep_kernel(const float* __restrict__ exp_m) {
    int i = blockIdx.x * blockDim.x + threadIdx.x;    // 16*256 = 4096
    float th = exp_m[i] + ETA_F;
    g_TL[i] = make_float2(th, th * __logf(th));
    if (i < KD) {
        g_invN[i] = 1.0f / (BETA_F * (float)VD + g_colEN[i]);
        g_invS[i] = 1.0f / (MU_F * g_colS[i] + g_colES[i]);
    }
}

// ---- shared layout offsets (bytes) for fused_kernel ----
#define SO_TL   0                      // float2[4096]            32768
#define SO_C    32768                  // float2[64*(VCH+1)]      16896
#define SO_C1T  49664                  // float [VCH*68]           8704
#define SO_W    58368                  // float [64*(VCH+1)]       8448
#define SO_FLAG 66816                  // int   [VCH]               128
#define SMEM_FUSED 66944

__global__ __launch_bounds__(256, 3) void fused_kernel(
    const float* __restrict__ BOW,
    const float* __restrict__ seeds,
    const float* __restrict__ exp_n,
    float* __restrict__ out)
{
    extern __shared__ char smem[];
    float2* sTL  = reinterpret_cast<float2*>(smem + SO_TL);
    float2* sC   = reinterpret_cast<float2*>(smem + SO_C);    // [k*(VCH+1)+vl] = (crr, crr*log crr)
    float*  sC1T = reinterpret_cast<float*>(smem + SO_C1T);   // [vl*68+k] = crr
    float*  sW   = reinterpret_cast<float*>(smem + SO_W);     // [b*(VCH+1)+vl]
    int*    sFlag= reinterpret_cast<int*>(smem + SO_FLAG);

    const int tid = threadIdx.x;
    const int v0 = blockIdx.x * VCH;
    const int vmax = min(VCH, VD - v0);

    for (int i = tid; i < BD * KD; i += 256) sTL[i] = g_TL[i];
    if (tid < VCH) sFlag[tid] = (tid < vmax) ? 0 : 1;   // invalid rows masked like seed rows
    __syncthreads();

    // ---- phase b: crr / crr*logcrr / flags ----
    for (int i = tid; i < VCH * KD; i += 256) {
        const int vl = i >> 6, k = i & 63;
        const int gv = v0 + vl;
        float c1 = 0.0f, cl = 0.0f;
        if (vl < vmax) {
            const float sd = seeds[gv * KD + k];
            const float en = exp_n[gv * KD + k];
            c1 = (1.0f - sd) * (BETA_F + en) * g_invN[k];
            cl = c1 * fast_log(c1 + 1e-30f);
            if (sd > 0.0f) sFlag[vl] = 1;
        }
        sC[k * (VCH + 1) + vl] = make_float2(c1, cl);
        sC1T[vl * 68 + k] = c1;
    }
    __syncthreads();

    // ---- GEMM1: rp[b,v], ab[b,v] over k; then elementwise -> W, qz ----
    const int tx = tid & 15;            // v-pair
    const int ty = tid >> 4;            // b-quad
    const int vg = tx * 2;
    const int bg = ty * 4;

    float rp[4][2] = {}, ab[4][2] = {};
    #pragma unroll 8
    for (int k = 0; k < KD; k++) {
        const float2 a0 = sTL[(bg + 0) * KD + k];
        const float2 a1 = sTL[(bg + 1) * KD + k];
        const float2 a2 = sTL[(bg + 2) * KD + k];
        const float2 a3 = sTL[(bg + 3) * KD + k];
        const float2 c0 = sC[k * (VCH + 1) + vg];
        const float2 c1 = sC[k * (VCH + 1) + vg + 1];
        rp[0][0] = fmaf(a0.x, c0.x, rp[0][0]); ab[0][0] = fmaf(a0.y, c0.x, fmaf(a0.x, c0.y, ab[0][0]));
        rp[0][1] = fmaf(a0.x, c1.x, rp[0][1]); ab[0][1] = fmaf(a0.y, c1.x, fmaf(a0.x, c1.y, ab[0][1]));
        rp[1][0] = fmaf(a1.x, c0.x, rp[1][0]); ab[1][0] = fmaf(a1.y, c0.x, fmaf(a1.x, c0.y, ab[1][0]));
        rp[1][1] = fmaf(a1.x, c1.x, rp[1][1]); ab[1][1] = fmaf(a1.y, c1.x, fmaf(a1.x, c1.y, ab[1][1]));
        rp[2][0] = fmaf(a2.x, c0.x, rp[2][0]); ab[2][0] = fmaf(a2.y, c0.x, fmaf(a2.x, c0.y, ab[2][0]));
        rp[2][1] = fmaf(a2.x, c1.x, rp[2][1]); ab[2][1] = fmaf(a2.y, c1.x, fmaf(a2.x, c1.y, ab[2][1]));
        rp[3][0] = fmaf(a3.x, c0.x, rp[3][0]); ab[3][0] = fmaf(a3.y, c0.x, fmaf(a3.x, c0.y, ab[3][0]));
        rp[3][1] = fmaf(a3.x, c1.x, rp[3][1]); ab[3][1] = fmaf(a3.y, c1.x, fmaf(a3.x, c1.y, ab[3][1]));
    }

    float qz = 0.0f;
    #pragma unroll
    for (int i = 0; i < 4; i++) {
        const int b = bg + i;
        #pragma unroll
        for (int j = 0; j < 2; j++) {
            const int vl = vg + j;
            float w = 0.0f;
            if (vl < vmax && sFlag[vl] == 0) {
                const float cnt = BOW[b * VD + v0 + vl];
                const float r = rp[i][j];
                const float rpm = r + MINI_F;
                const float inv = __fdividef(1.0f, rpm);
                w = cnt * inv;
                if (cnt > 0.0f)
                    qz += ab[i][j] * inv - fast_log(rpm) * (r * inv);
            }
            sW[b * (VCH + 1) + vl] = w;
        }
    }
    __syncthreads();

    // ---- GEMM2: temp_exp_n[v,k] = crr * sum_b W[b,v]*theta[b,k]; ES zeros ----
    {
        const int kg = (tid & 15) * 4;
        const int vg2 = (tid >> 4) * 2;
        float en[2][4] = {};
        #pragma unroll 4
        for (int b = 0; b < BD; b++) {
            const float w0 = sW[b * (VCH + 1) + vg2];
            const float w1 = sW[b * (VCH + 1) + vg2 + 1];
            const float4 p0 = *reinterpret_cast<const float4*>(&sTL[b * KD + kg]);
            const float4 p1 = *reinterpret_cast<const float4*>(&sTL[b * KD + kg + 2]);
            en[0][0] = fmaf(w0, p0.x, en[0][0]); en[0][1] = fmaf(w0, p0.z, en[0][1]);
            en[0][2] = fmaf(w0, p1.x, en[0][2]); en[0][3] = fmaf(w0, p1.z, en[0][3]);
            en[1][0] = fmaf(w1, p0.x, en[1][0]); en[1][1] = fmaf(w1, p0.z, en[1][1]);
            en[1][2] = fmaf(w1, p1.x, en[1][2]); en[1][3] = fmaf(w1, p1.z, en[1][3]);
        }
        #pragma unroll
        for (int i = 0; i < 2; i++) {
            const int vl = vg2 + i;
            if (vl < vmax) {
                const float4 c4 = *reinterpret_cast<const float4*>(&sC1T[vl * 68 + kg]);
                float4 o;
                o.x = en[i][0] * c4.x; o.y = en[i][1] * c4.y;
                o.z = en[i][2] * c4.z; o.w = en[i][3] * c4.w;
                const int gv = v0 + vl;
                *reinterpret_cast<float4*>(&out[OFF_N + gv * KD + kg]) = o;
                *reinterpret_cast<float4*>(&out[OFF_S + gv * KD + kg]) = make_float4(0.f, 0.f, 0.f, 0.f);
            }
        }
    }

    // ---- GEMM3: P[b,k] += sum_v W[b,v]*crr[v,k] ----
    {
        const int kg = (tid & 15) * 4;
        const int bg3 = (tid >> 4) * 4;
        float p[4][4] = {};
        #pragma unroll 4
        for (int vl = 0; vl < VCH; vl++) {
            const float4 c4 = *reinterpret_cast<const float4*>(&sC1T[vl * 68 + kg]);
            const float w0 = sW[(bg3 + 0) * (VCH + 1) + vl];
            const float w1 = sW[(bg3 + 1) * (VCH + 1) + vl];
            const float w2 = sW[(bg3 + 2) * (VCH + 1) + vl];
            const float w3 = sW[(bg3 + 3) * (VCH + 1) + vl];
            p[0][0] = fmaf(w0, c4.x, p[0][0]); p[0][1] = fmaf(w0, c4.y, p[0][1]);
            p[0][2] = fmaf(w0, c4.z, p[0][2]); p[0][3] = fmaf(w0, c4.w, p[0][3]);
            p[1][0] = fmaf(w1, c4.x, p[1][0]); p[1][1] = fmaf(w1, c4.y, p[1][1]);
            p[1][2] = fmaf(w1, c4.z, p[1][2]); p[1][3] = fmaf(w1, c4.w, p[1][3]);
            p[2][0] = fmaf(w2, c4.x, p[2][0]); p[2][1] = fmaf(w2, c4.y, p[2][1]);
            p[2][2] = fmaf(w2, c4.z, p[2][2]); p[2][3] = fmaf(w2, c4.w, p[2][3]);
            p[3][0] = fmaf(w3, c4.x, p[3][0]); p[3][1] = fmaf(w3, c4.y, p[3][1]);
            p[3][2] = fmaf(w3, c4.z, p[3][2]); p[3][3] = fmaf(w3, c4.w, p[3][3]);
        }
        float* dst = g_P32 + (blockIdx.x & (NSLICE - 1)) * (BD * KD);
        #pragma unroll
        for (int i = 0; i < 4; i++)
            #pragma unroll
            for (int j = 0; j < 4; j++)
                atomicAdd(&dst[(bg3 + i) * KD + kg + j], p[i][j]);
    }

    // ---- qz: warp -> one atomic per block ----
    qz = warp_sum(qz);
    __shared__ float sQz;
    if (tid == 0) sQz = 0.0f;
    __syncthreads();
    if ((tid & 31) == 0 && qz != 0.0f) atomicAdd(&sQz, qz);
    __syncthreads();
    if (tid == 0 && sQz != 0.0f) atomicAdd(&out[OFF_QZ], sQz);
}

// ---- exact path for the seed rows (~640 of 10000) ----
__global__ __launch_bounds__(256) void seed_kernel(
    const float* __restrict__ BOW,
    const float* __restrict__ seeds,
    const float* __restrict__ exp_s,
    const float* __restrict__ exp_n,
    const float* __restrict__ pi,
    float* __restrict__ out)
{
    __shared__ float sTh[BD * KD];
    const int tid = threadIdx.x;
    for (int i = tid; i < BD * KD; i += 256) sTh[i] = g_TL[i].x;
    __syncthreads();

    const int lane = tid & 31, warp = tid >> 5;
    const int gwarp = blockIdx.x * 8 + warp;
    const int nwarp = gridDim.x * 8;
    const int k0 = lane, k1 = lane + 32;
    const float invS0 = g_invS[k0], invS1 = g_invS[k1];
    const float invN0 = g_invN[k0], invN1 = g_invN[k1];
    const float pi0 = pi[k0], pi1 = pi[k1];
    const float q0 = 1.0f - pi0, q1 = 1.0f - pi1;

    float accGsr0 = 0.0f, accGsr1 = 0.0f, accQz = 0.0f;

    for (int v = gwarp; v < VD; v += nwarp) {
        const int base = v * KD;
        const float sd0 = seeds[base + k0], sd1 = seeds[base + k1];
        if (!__any_sync(0xffffffffu, (sd0 > 0.0f) || (sd1 > 0.0f))) continue;

        const float ps0 = (MU_F  + exp_s[base + k0]) * invS0;
        const float ps1 = (MU_F  + exp_s[base + k1]) * invS1;
        const float pn0 = (BETA_F + exp_n[base + k0]) * invN0;
        const float pn1 = (BETA_F + exp_n[base + k1]) * invN1;
        const float crr0 = (1.0f - sd0) * pn0, crr1 = (1.0f - sd1) * pn1;
        const float css0 = sd0 * ps0 * pi0, css1 = sd1 * ps1 * pi1;
        const float csr0 = sd0 * pn0 * q0,  csr1 = sd1 * pn1 * q1;

        const float cntA = BOW[lane * VD + v];
        const float cntB = BOW[(lane + 32) * VD + v];

        float aN0 = 0.f, aN1 = 0.f, aS0 = 0.f, aS1 = 0.f;

        for (int b = 0; b < BD; b++) {
            const float cnt = __shfl_sync(0xffffffffu, (b < 32) ? cntA : cntB, b & 31);
            if (cnt <= 0.0f) continue;
            const float th0 = sTh[b * KD + k0];
            const float th1 = sTh[b * KD + k1];
            float gss0 = th0 * css0, gss1 = th1 * css1;
            float gsr0 = th0 * csr0, gsr1 = th1 * csr1;
            float grr0 = th0 * crr0, grr1 = th1 * crr1;
            float sp = gss0 + gsr0 + gss1 + gsr1;
            float rp = grr0 + grr1;
            #pragma unroll
            for (int o = 16; o; o >>= 1) {
                sp += __shfl_xor_sync(0xffffffffu, sp, o);
                rp += __shfl_xor_sync(0xffffffffu, rp, o);
            }
            const float invs = __fdividef(1.0f, sp + MINI_F);
            const float invr = __fdividef(1.0f, rp + MINI_F);
            gss0 *= invs; gss1 *= invs;
            gsr0 *= invs; gsr1 *= invs;
            grr0 *= invr; grr1 *= invr;
            const float gam0 = pi0 * gss0 + q0 * (gsr0 + grr0);
            const float gam1 = pi1 * gss1 + q1 * (gsr1 + grr1);
            aN0 += (gsr0 + grr0) * cnt; aN1 += (gsr1 + grr1) * cnt;
            aS0 += gss0 * cnt;          aS1 += gss1 * cnt;
            accGsr0 += gsr0;            accGsr1 += gsr1;
            accQz += gam0 * __logf(gam0 + MINI_F) + gam1 * __logf(gam1 + MINI_F);
            atomicAdd(&g_Mseed[b * KD + k0], gam0 * cnt);
            atomicAdd(&g_Mseed[b * KD + k1], gam1 * cnt);
        }
        out[OFF_N + base + k0] = aN0; out[OFF_N + base + k1] = aN1;
        out[OFF_S + base + k0] = aS0; out[OFF_S + base + k1] = aS1;
    }

    if (accGsr0 != 0.0f) atomicAdd(&out[OFF_GSR + k0], accGsr0);
    if (accGsr1 != 0.0f) atomicAdd(&out[OFF_GSR + k1], accGsr1);
    accQz = warp_sum(accQz);
    if (lane == 0 && accQz != 0.0f) atomicAdd(&out[OFF_QZ], accQz);
}

__global__ void finalize_kernel(float* __restrict__ out) {
    const int i = blockIdx.x * blockDim.x + threadIdx.x;   // 16*256 = 4096
    float s = 0.0f;
    #pragma unroll
    for (int j = 0; j < NSLICE; j++)
        s += g_P32[j * (BD * KD) + i];
    out[i] = g_TL[i].x * s + g_Mseed[i];
}

extern "C" void kernel_launch(void* const* d_in, const int* in_sizes, int n_in,
                              void* d_out, int out_size) {
    const float* BOW   = (const float*)d_in[0];
    const float* seeds = (const float*)d_in[1];
    const float* exp_m = (const float*)d_in[2];
    const float* exp_s = (const float*)d_in[3];
    const float* exp_n = (const float*)d_in[4];
    const float* pi    = (const float*)d_in[5];
    float* out = (float*)d_out;

    static int smem_set = 0;
    if (!smem_set) {
        cudaFuncSetAttribute(fused_kernel, cudaFuncAttributeMaxDynamicSharedMemorySize, SMEM_FUSED);
        smem_set = 1;
    }

    zero_kernel<<<128, 256>>>(out);
    colsum_kernel<<<592, 256>>>(seeds, exp_s, exp_n);
    prep_kernel<<<16, 256>>>(exp_m);
    fused_kernel<<<NCH, 256, SMEM_FUSED>>>(BOW, seeds, exp_n, out);
    seed_kernel<<<296, 256>>>(BOW, seeds, exp_s, exp_n, pi, out);
    finalize_kernel<<<16, 256>>>(out);
}

// round 12
// speedup vs baseline: 1.0821x; 1.0821x over previous
#include <cuda_runtime.h>

// MixEHR_Seed: B=64, V=10000, K=64 — GEMM-factorized formulation v2.
// out: temp_exp_m_batch [64,64], temp_exp_n [V,K], temp_exp_s [V,K], gamma_sr_sum [K], exp_q_z [1]

#define KD     64
#define BD     64
#define VD     10000
#define VCH    16
#define NCH    625            // VD / VCH exactly
#define ETA_F  0.1f
#define BETA_F 0.05f
#define MU_F   0.05f
#define MINI_F 1e-6f

#define OFF_N   4096
#define OFF_S   644096
#define OFF_GSR 1284096
#define OFF_QZ  1284160

__device__ float  g_colS[KD];
__device__ float  g_colES[KD];
__device__ float  g_colEN[KD];
__device__ float  g_invN[KD];
__device__ float  g_invS[KD];
__device__ float2 g_TL[BD * KD];        // (theta, theta*log theta)
__device__ float  g_P[NCH * BD * KD];   // per-block W@crr partials (10.24 MB)
__device__ float  g_Mseed[BD * KD];
__device__ int    g_nseed;
__device__ int    g_seedlist[VD];
__device__ int    g_flag[VD];

__device__ __forceinline__ float warp_sum(float x) {
    #pragma unroll
    for (int o = 16; o; o >>= 1)
        x += __shfl_xor_sync(0xffffffffu, x, o);
    return x;
}

// ln(x) for positive normal x, FMA-pipe only. |err| ~2e-6.
__device__ __forceinline__ float fast_log(float x) {
    int ix = __float_as_int(x);
    int e  = (ix - 0x3f330000) >> 23;
    float m = __int_as_float(ix - (e << 23));
    float f = m - 1.0f;
    float p = 0.09090909f;
    p = fmaf(p, f, -0.1f);
    p = fmaf(p, f,  0.11111111f);
    p = fmaf(p, f, -0.125f);
    p = fmaf(p, f,  0.14285714f);
    p = fmaf(p, f, -0.16666667f);
    p = fmaf(p, f,  0.2f);
    p = fmaf(p, f, -0.25f);
    p = fmaf(p, f,  0.33333333f);
    p = fmaf(p, f, -0.5f);
    p = fmaf(p, f,  1.0f);
    return fmaf((float)e, 0.69314718f, p * f);
}

__global__ void zero_kernel(float* out) {
    int i = blockIdx.x * blockDim.x + threadIdx.x;   // 16*256 = 4096
    out[i] = 0.0f;                                   // temp_exp_m_batch
    g_Mseed[i] = 0.0f;
    if (i < KD) {
        out[OFF_GSR + i] = 0.0f;
        g_colS[i] = 0.0f; g_colES[i] = 0.0f; g_colEN[i] = 0.0f;
    }
    if (i == 0) { out[OFF_QZ] = 0.0f; g_nseed = 0; }
}

__global__ void colsum_kernel(const float* __restrict__ seeds,
                              const float* __restrict__ exp_s,
                              const float* __restrict__ exp_n) {
    int tid = blockIdx.x * blockDim.x + threadIdx.x;
    int stride = gridDim.x * blockDim.x;
    float a = 0.0f, b = 0.0f, c = 0.0f;
    for (int i = tid; i < VD * KD; i += stride) {
        a += seeds[i]; b += exp_s[i]; c += exp_n[i];
    }
    int k = tid & (KD - 1);
    atomicAdd(&g_colS[k], a);
    atomicAdd(&g_colES[k], b);
    atomicAdd(&g_colEN[k], c);
}

__global__ void prep_kernel(const float* __restrict__ exp_m) {
    int i = blockIdx.x * blockDim.x + threadIdx.x;   // 16*256 = 4096
    float th = exp_m[i] + ETA_F;
    g_TL[i] = make_float2(th, th * __logf(th));
    if (i < KD) {
        g_invN[i] = 1.0f / (BETA_F * (float)VD + g_colEN[i]);
        g_invS[i] = 1.0f / (MU_F * g_colS[i] + g_colES[i]);
    }
}

__global__ void flag_kernel(const float* __restrict__ seeds) {
    int v = blockIdx.x * blockDim.x + threadIdx.x;   // 40*256 >= 10000
    if (v >= VD) return;
    const float4* sr = reinterpret_cast<const float4*>(seeds + v * KD);
    int f = 0;
    #pragma unroll
    for (int q = 0; q < 16; q++) {
        float4 s4 = sr[q];
        f |= (s4.x > 0.0f) | (s4.y > 0.0f) | (s4.z > 0.0f) | (s4.w > 0.0f);
    }
    g_flag[v] = f;
    if (f) {
        int pos = atomicAdd(&g_nseed, 1);
        g_seedlist[pos] = v;
    }
}

// ---- fused GEMM kernel: non-seed rows ----
#define SO_TL   0                      // float2[4096]           32768
#define SO_C    32768                  // float2[64*17]           8704
#define SO_C1T  41472                  // float [16*68]           4352
#define SO_W    45824                  // float [64*17]           4352
#define SO_FLAG 50176                  // int   [16]                64
#define SO_QZ   50240                  // float                     4
#define SMEM_FUSED 50304

__global__ __launch_bounds__(256, 4) void fused_kernel(
    const float* __restrict__ BOW,
    const float* __restrict__ seeds,
    const float* __restrict__ exp_n,
    float* __restrict__ out)
{
    extern __shared__ char smem[];
    float2* sTL  = reinterpret_cast<float2*>(smem + SO_TL);
    float2* sC   = reinterpret_cast<float2*>(smem + SO_C);    // [k*17+vl] = (crr, crr*log crr)
    float*  sC1T = reinterpret_cast<float*>(smem + SO_C1T);   // [vl*68+k] = crr
    float*  sW   = reinterpret_cast<float*>(smem + SO_W);     // [b*17+vl]
    int*    sFlag= reinterpret_cast<int*>(smem + SO_FLAG);
    float*  sQz  = reinterpret_cast<float*>(smem + SO_QZ);

    const int tid = threadIdx.x;
    const int v0 = blockIdx.x * VCH;

    for (int i = tid; i < BD * KD; i += 256) sTL[i] = g_TL[i];
    if (tid < VCH) sFlag[tid] = g_flag[v0 + tid];
    if (tid == 0) *sQz = 0.0f;

    // crr / crr*logcrr
    #pragma unroll
    for (int r = 0; r < 4; r++) {
        const int i = tid + r * 256;        // 0..1023
        const int vl = i >> 6, k = i & 63;
        const float sd = seeds[(v0 + vl) * KD + k];
        const float en = exp_n[(v0 + vl) * KD + k];
        const float c1 = (1.0f - sd) * (BETA_F + en) * g_invN[k];
        const float cl = c1 * fast_log(c1 + 1e-30f);
        sC[k * 17 + vl] = make_float2(c1, cl);
        sC1T[vl * 68 + k] = c1;
    }
    __syncthreads();

    // ---- GEMM1: rp/ab over k; elementwise -> W, qz ----
    float qz = 0.0f;
    {
        const int tx = tid & 7,  ty = tid >> 3;
        const int vg = tx * 2,   bg = ty * 2;
        float rp00=0,rp01=0,rp10=0,rp11=0;
        float ab00=0,ab01=0,ab10=0,ab11=0;
        #pragma unroll 8
        for (int k = 0; k < KD; k++) {
            const float2 a0 = sTL[bg * KD + k];
            const float2 a1 = sTL[(bg + 1) * KD + k];
            const float2 c0 = sC[k * 17 + vg];
            const float2 c1 = sC[k * 17 + vg + 1];
            rp00 = fmaf(a0.x, c0.x, rp00); ab00 = fmaf(a0.y, c0.x, fmaf(a0.x, c0.y, ab00));
            rp01 = fmaf(a0.x, c1.x, rp01); ab01 = fmaf(a0.y, c1.x, fmaf(a0.x, c1.y, ab01));
            rp10 = fmaf(a1.x, c0.x, rp10); ab10 = fmaf(a1.y, c0.x, fmaf(a1.x, c0.y, ab10));
            rp11 = fmaf(a1.x, c1.x, rp11); ab11 = fmaf(a1.y, c1.x, fmaf(a1.x, c1.y, ab11));
        }
        const int f0 = sFlag[vg], f1 = sFlag[vg + 1];
        #pragma unroll
        for (int e = 0; e < 4; e++) {
            const int i = e >> 1, j = e & 1;
            const float r  = (e==0)?rp00:(e==1)?rp01:(e==2)?rp10:rp11;
            const float a  = (e==0)?ab00:(e==1)?ab01:(e==2)?ab10:ab11;
            const int b = bg + i, vl = vg + j;
            float w = 0.0f;
            if (((j == 0) ? f0 : f1) == 0) {
                const float cnt = BOW[b * VD + v0 + vl];
                const float rpm = r + MINI_F;
                const float inv = __fdividef(1.0f, rpm);
                w = cnt * inv;
                if (cnt > 0.0f)
                    qz += a * inv - fast_log(rpm) * (r * inv);
            }
            sW[b * 17 + vl] = w;
        }
    }
    __syncthreads();

    // ---- GEMM2: EN[v,k] = crr * sum_b W[b,v]*theta[b,k]; ES zeros ----
    {
        const int vl = tid & 15;
        const int kg = (tid >> 4) * 4;
        float e0=0,e1=0,e2=0,e3=0;
        #pragma unroll 4
        for (int b = 0; b < BD; b++) {
            const float w = sW[b * 17 + vl];
            const float4 p0 = *reinterpret_cast<const float4*>(&sTL[b * KD + kg]);
            const float4 p1 = *reinterpret_cast<const float4*>(&sTL[b * KD + kg + 2]);
            e0 = fmaf(w, p0.x, e0); e1 = fmaf(w, p0.z, e1);
            e2 = fmaf(w, p1.x, e2); e3 = fmaf(w, p1.z, e3);
        }
        const float4 c4 = *reinterpret_cast<const float4*>(&sC1T[vl * 68 + kg]);
        float4 o;
        o.x = e0 * c4.x; o.y = e1 * c4.y; o.z = e2 * c4.z; o.w = e3 * c4.w;
        const int gv = v0 + vl;
        *reinterpret_cast<float4*>(&out[OFF_N + gv * KD + kg]) = o;
        *reinterpret_cast<float4*>(&out[OFF_S + gv * KD + kg]) = make_float4(0.f, 0.f, 0.f, 0.f);
    }

    // ---- GEMM3: P[b,k] = sum_v W[b,v]*crr[v,k] (reads-only since last sync) ----
    {
        const int kg  = (tid & 15) * 4;
        const int bg3 = (tid >> 4) * 4;
        float p[4][4] = {};
        #pragma unroll 4
        for (int vl = 0; vl < VCH; vl++) {
            const float4 c4 = *reinterpret_cast<const float4*>(&sC1T[vl * 68 + kg]);
            const float w0 = sW[(bg3 + 0) * 17 + vl];
            const float w1 = sW[(bg3 + 1) * 17 + vl];
            const float w2 = sW[(bg3 + 2) * 17 + vl];
            const float w3 = sW[(bg3 + 3) * 17 + vl];
            p[0][0]=fmaf(w0,c4.x,p[0][0]); p[0][1]=fmaf(w0,c4.y,p[0][1]); p[0][2]=fmaf(w0,c4.z,p[0][2]); p[0][3]=fmaf(w0,c4.w,p[0][3]);
            p[1][0]=fmaf(w1,c4.x,p[1][0]); p[1][1]=fmaf(w1,c4.y,p[1][1]); p[1][2]=fmaf(w1,c4.z,p[1][2]); p[1][3]=fmaf(w1,c4.w,p[1][3]);
            p[2][0]=fmaf(w2,c4.x,p[2][0]); p[2][1]=fmaf(w2,c4.y,p[2][1]); p[2][2]=fmaf(w2,c4.z,p[2][2]); p[2][3]=fmaf(w2,c4.w,p[2][3]);
            p[3][0]=fmaf(w3,c4.x,p[3][0]); p[3][1]=fmaf(w3,c4.y,p[3][1]); p[3][2]=fmaf(w3,c4.z,p[3][2]); p[3][3]=fmaf(w3,c4.w,p[3][3]);
        }
        float* dst = g_P + blockIdx.x * (BD * KD);
        #pragma unroll
        for (int i = 0; i < 4; i++)
            *reinterpret_cast<float4*>(&dst[(bg3 + i) * KD + kg]) =
                make_float4(p[i][0], p[i][1], p[i][2], p[i][3]);
    }

    // qz: warp -> shared -> one global atomic per block
    qz = warp_sum(qz);
    __syncthreads();
    if ((tid & 31) == 0 && qz != 0.0f) atomicAdd(sQz, qz);
    __syncthreads();
    if (tid == 0 && *sQz != 0.0f) atomicAdd(&out[OFF_QZ], *sQz);
}

// ---- exact path for the seed rows; 2 warps per row (b-halves) ----
__global__ __launch_bounds__(256) void seed_kernel(
    const float* __restrict__ BOW,
    const float* __restrict__ seeds,
    const float* __restrict__ exp_s,
    const float* __restrict__ exp_n,
    const float* __restrict__ pi,
    float* __restrict__ out)
{
    __shared__ float sTh[BD * KD];
    const int tid = threadIdx.x;
    for (int i = tid; i < BD * KD; i += 256) sTh[i] = g_TL[i].x;
    __syncthreads();

    const int lane = tid & 31, warp = tid >> 5;
    const int gw = blockIdx.x * 8 + warp;
    const int nwarp = gridDim.x * 8;
    const int k0 = lane, k1 = lane + 32;
    const float invS0 = g_invS[k0], invS1 = g_invS[k1];
    const float invN0 = g_invN[k0], invN1 = g_invN[k1];
    const float pi0 = pi[k0], pi1 = pi[k1];
    const float q0 = 1.0f - pi0, q1 = 1.0f - pi1;
    const int nseed = g_nseed;

    float accGsr0 = 0.0f, accGsr1 = 0.0f, accQz = 0.0f;

    for (int idx = gw; idx < 2 * nseed; idx += nwarp) {
        const int v = g_seedlist[idx >> 1];
        const int bbase = (idx & 1) * 32;
        const int base = v * KD;

        const float sd0 = seeds[base + k0], sd1 = seeds[base + k1];
        const float ps0 = (MU_F  + exp_s[base + k0]) * invS0;
        const float ps1 = (MU_F  + exp_s[base + k1]) * invS1;
        const float pn0 = (BETA_F + exp_n[base + k0]) * invN0;
        const float pn1 = (BETA_F + exp_n[base + k1]) * invN1;
        const float crr0 = (1.0f - sd0) * pn0, crr1 = (1.0f - sd1) * pn1;
        const float css0 = sd0 * ps0 * pi0, css1 = sd1 * ps1 * pi1;
        const float csr0 = sd0 * pn0 * q0,  csr1 = sd1 * pn1 * q1;

        const float cntA = BOW[(bbase + lane) * VD + v];

        float aN0 = 0.f, aN1 = 0.f, aS0 = 0.f, aS1 = 0.f;

        for (int bb = 0; bb < 32; bb++) {
            const float cnt = __shfl_sync(0xffffffffu, cntA, bb);
            if (cnt <= 0.0f) continue;
            const int b = bbase + bb;
            const float th0 = sTh[b * KD + k0];
            const float th1 = sTh[b * KD + k1];
            float gss0 = th0 * css0, gss1 = th1 * css1;
            float gsr0 = th0 * csr0, gsr1 = th1 * csr1;
            float grr0 = th0 * crr0, grr1 = th1 * crr1;
            float sp = gss0 + gsr0 + gss1 + gsr1;
            float rp = grr0 + grr1;
            #pragma unroll
            for (int o = 16; o; o >>= 1) {
                sp += __shfl_xor_sync(0xffffffffu, sp, o);
                rp += __shfl_xor_sync(0xffffffffu, rp, o);
            }
            const float invs = __fdividef(1.0f, sp + MINI_F);
            const float invr = __fdividef(1.0f, rp + MINI_F);
            gss0 *= invs; gss1 *= invs;
            gsr0 *= invs; gsr1 *= invs;
            grr0 *= invr; grr1 *= invr;
            const float gam0 = pi0 * gss0 + q0 * (gsr0 + grr0);
            const float gam1 = pi1 * gss1 + q1 * (gsr1 + grr1);
            aN0 += (gsr0 + grr0) * cnt; aN1 += (gsr1 + grr1) * cnt;
            aS0 += gss0 * cnt;          aS1 += gss1 * cnt;
            accGsr0 += gsr0;            accGsr1 += gsr1;
            accQz += gam0 * __logf(gam0 + MINI_F) + gam1 * __logf(gam1 + MINI_F);
            atomicAdd(&g_Mseed[b * KD + k0], gam0 * cnt);
            atomicAdd(&g_Mseed[b * KD + k1], gam1 * cnt);
        }
        // fused wrote zeros for flagged rows; combine two half-warps via atomics
        if (aN0 != 0.0f) atomicAdd(&out[OFF_N + base + k0], aN0);
        if (aN1 != 0.0f) atomicAdd(&out[OFF_N + base + k1], aN1);
        if (aS0 != 0.0f) atomicAdd(&out[OFF_S + base + k0], aS0);
        if (aS1 != 0.0f) atomicAdd(&out[OFF_S + base + k1], aS1);
    }

    if (accGsr0 != 0.0f) atomicAdd(&out[OFF_GSR + k0], accGsr0);
    if (accGsr1 != 0.0f) atomicAdd(&out[OFF_GSR + k1], accGsr1);
    accQz = warp_sum(accQz);
    if (lane == 0 && accQz != 0.0f) atomicAdd(&out[OFF_QZ], accQz);
}

// out[i] += theta[i] * sum over 25 P-slices (y of 25 chunks); y==0 adds Mseed.
__global__ void finalize_kernel(float* __restrict__ out) {
    const int i = blockIdx.x * blockDim.x + threadIdx.x;   // 0..4095
    const int j0 = blockIdx.y * 25;
    float s = 0.0f;
    #pragma unroll 5
    for (int j = 0; j < 25; j++)
        s += g_P[(j0 + j) * (BD * KD) + i];
    float add = g_TL[i].x * s;
    if (blockIdx.y == 0) add += g_Mseed[i];
    atomicAdd(&out[i], add);
}

extern "C" void kernel_launch(void* const* d_in, const int* in_sizes, int n_in,
                              void* d_out, int out_size) {
    const float* BOW   = (const float*)d_in[0];
    const float* seeds = (const float*)d_in[1];
    const float* exp_m = (const float*)d_in[2];
    const float* exp_s = (const float*)d_in[3];
    const float* exp_n = (const float*)d_in[4];
    const float* pi    = (const float*)d_in[5];
    float* out = (float*)d_out;

    static int smem_set = 0;
    if (!smem_set) {
        cudaFuncSetAttribute(fused_kernel, cudaFuncAttributeMaxDynamicSharedMemorySize, SMEM_FUSED);
        smem_set = 1;
    }

    zero_kernel<<<16, 256>>>(out);
    colsum_kernel<<<592, 256>>>(seeds, exp_s, exp_n);
    prep_kernel<<<16, 256>>>(exp_m);
    flag_kernel<<<40, 256>>>(seeds);
    fused_kernel<<<NCH, 256, SMEM_FUSED>>>(BOW, seeds, exp_n, out);
    seed_kernel<<<160, 256>>>(BOW, seeds, exp_s, exp_n, pi, out);
    finalize_kernel<<<dim3(16, 25), 256>>>(out);
}

// round 13
// speedup vs baseline: 1.1706x; 1.0818x over previous
#include <cuda_runtime.h>

// MixEHR_Seed: B=64, V=10000, K=64 — GEMM-factorized formulation v3.
// out: temp_exp_m_batch [64,64], temp_exp_n [V,K], temp_exp_s [V,K], gamma_sr_sum [K], exp_q_z [1]

#define KD     64
#define BD     64
#define VD     10000
#define VCH    16
#define NCH    625            // VD / VCH exactly
#define ETA_F  0.1f
#define BETA_F 0.05f
#define MU_F   0.05f
#define MINI_F 1e-6f

#define OFF_N   4096
#define OFF_S   644096
#define OFF_GSR 1284096
#define OFF_QZ  1284160

__device__ float  g_colS[KD];
__device__ float  g_colES[KD];
__device__ float  g_colEN[KD];
__device__ float  g_invN[KD];
__device__ float  g_invS[KD];
__device__ float2 g_TL[BD * KD];        // (theta, theta*log theta)
__device__ float  g_P[NCH * BD * KD];   // per-block W@crr partials (10.24 MB)
__device__ float  g_Mseed[BD * KD];
__device__ int    g_nseed;              // reset by finalize each run; 0 at module load
__device__ int    g_seedlist[VD];
__device__ int    g_flag[VD];

__device__ __forceinline__ float warp_sum(float x) {
    #pragma unroll
    for (int o = 16; o; o >>= 1)
        x += __shfl_xor_sync(0xffffffffu, x, o);
    return x;
}

// ln(x) for positive normal x, FMA-pipe only. |err| ~2e-6.
__device__ __forceinline__ float fast_log(float x) {
    int ix = __float_as_int(x);
    int e  = (ix - 0x3f330000) >> 23;
    float m = __int_as_float(ix - (e << 23));
    float f = m - 1.0f;
    float p = 0.09090909f;
    p = fmaf(p, f, -0.1f);
    p = fmaf(p, f,  0.11111111f);
    p = fmaf(p, f, -0.125f);
    p = fmaf(p, f,  0.14285714f);
    p = fmaf(p, f, -0.16666667f);
    p = fmaf(p, f,  0.2f);
    p = fmaf(p, f, -0.25f);
    p = fmaf(p, f,  0.33333333f);
    p = fmaf(p, f, -0.5f);
    p = fmaf(p, f,  1.0f);
    return fmaf((float)e, 0.69314718f, p * f);
}

// zero + flag/seedlist build. grid 79 x 256 (2 threads per v-row).
// g_nseed is 0 on entry (module load / finalize of previous run).
__global__ void zeroflag_kernel(const float* __restrict__ seeds, float* out) {
    const int i = blockIdx.x * blockDim.x + threadIdx.x;   // 0..20223
    if (i < BD * KD) { out[i] = 0.0f; g_Mseed[i] = 0.0f; }
    if (i < KD) {
        out[OFF_GSR + i] = 0.0f;
        g_colS[i] = 0.0f; g_colES[i] = 0.0f; g_colEN[i] = 0.0f;
    }
    if (i == 0) out[OFF_QZ] = 0.0f;

    const int row = i >> 1, half = i & 1;
    int f = 0;
    if (row < VD) {
        const float4* sr = reinterpret_cast<const float4*>(seeds + row * KD + half * 32);
        #pragma unroll
        for (int q = 0; q < 8; q++) {
            float4 s4 = sr[q];
            f |= (s4.x > 0.0f) | (s4.y > 0.0f) | (s4.z > 0.0f) | (s4.w > 0.0f);
        }
    }
    f |= __shfl_xor_sync(0xffffffffu, f, 1);
    if (row < VD && half == 0) {
        g_flag[row] = f;
        if (f) {
            int pos = atomicAdd(&g_nseed, 1);
            g_seedlist[pos] = row;
        }
    }
}

__global__ void colsum_kernel(const float* __restrict__ seeds,
                              const float* __restrict__ exp_s,
                              const float* __restrict__ exp_n) {
    int tid = blockIdx.x * blockDim.x + threadIdx.x;
    int stride = gridDim.x * blockDim.x;
    float a = 0.0f, b = 0.0f, c = 0.0f;
    for (int i = tid; i < VD * KD; i += stride) {
        a += seeds[i]; b += exp_s[i]; c += exp_n[i];
    }
    int k = tid & (KD - 1);
    atomicAdd(&g_colS[k], a);
    atomicAdd(&g_colES[k], b);
    atomicAdd(&g_colEN[k], c);
}

__global__ void prep_kernel(const float* __restrict__ exp_m) {
    int i = blockIdx.x * blockDim.x + threadIdx.x;   // 16*256 = 4096
    float th = exp_m[i] + ETA_F;
    g_TL[i] = make_float2(th, th * __logf(th));
    if (i < KD) {
        g_invN[i] = 1.0f / (BETA_F * (float)VD + g_colEN[i]);
        g_invS[i] = 1.0f / (MU_F * g_colS[i] + g_colES[i]);
    }
}

// ---- fused GEMM kernel: non-seed rows ----
// smem layout (bytes):
//   sTh   float[4096]   16384  @0       theta plane
//   sThL  float[4096]   16384  @16384   theta*log(theta) plane
//   sC    float2[64*17]  8704  @32768   (crr, crr*logcrr), k-major
//   sC1T  float[16*68]   4352  @41472   crr, v-major (float4-readable)
//   sW    float[64*17]   4352  @45824
//   sFlag int[16]          64  @50176
//   sQz   float             4  @50240
#define SO_TH   0
#define SO_THL  16384
#define SO_C    32768
#define SO_C1T  41472
#define SO_W    45824
#define SO_FLAG 50176
#define SO_QZ   50240
#define SMEM_FUSED 50304

__global__ __launch_bounds__(256, 4) void fused_kernel(
    const float* __restrict__ BOW,
    const float* __restrict__ seeds,
    const float* __restrict__ exp_n,
    float* __restrict__ out)
{
    extern __shared__ char smem[];
    float*  sTh  = reinterpret_cast<float*>(smem + SO_TH);
    float*  sThL = reinterpret_cast<float*>(smem + SO_THL);
    float2* sC   = reinterpret_cast<float2*>(smem + SO_C);
    float*  sC1T = reinterpret_cast<float*>(smem + SO_C1T);
    float*  sW   = reinterpret_cast<float*>(smem + SO_W);
    int*    sFlag= reinterpret_cast<int*>(smem + SO_FLAG);
    float*  sQz  = reinterpret_cast<float*>(smem + SO_QZ);

    const int tid = threadIdx.x;
    const int v0 = blockIdx.x * VCH;

    for (int i = tid; i < BD * KD; i += 256) {
        const float2 tl = g_TL[i];
        sTh[i] = tl.x;
        sThL[i] = tl.y;
    }
    if (tid < VCH) sFlag[tid] = g_flag[v0 + tid];
    if (tid == 0) *sQz = 0.0f;

    // crr / crr*logcrr
    #pragma unroll
    for (int r = 0; r < 4; r++) {
        const int i = tid + r * 256;        // 0..1023
        const int vl = i >> 6, k = i & 63;
        const float sd = seeds[(v0 + vl) * KD + k];
        const float en = exp_n[(v0 + vl) * KD + k];
        const float c1 = (1.0f - sd) * (BETA_F + en) * g_invN[k];
        const float cl = c1 * fast_log(c1 + 1e-30f);
        sC[k * 17 + vl] = make_float2(c1, cl);
        sC1T[vl * 68 + k] = c1;
    }
    __syncthreads();

    // ---- GEMM1: rp/ab over k; elementwise -> W, qz ----
    float qz = 0.0f;
    {
        const int tx = tid & 7,  ty = tid >> 3;
        const int vg = tx * 2,   bg = ty * 2;
        float rp00=0,rp01=0,rp10=0,rp11=0;
        float ab00=0,ab01=0,ab10=0,ab11=0;
        #pragma unroll 8
        for (int k = 0; k < KD; k++) {
            const float a0x = sTh [bg * KD + k];
            const float a0y = sThL[bg * KD + k];
            const float a1x = sTh [(bg + 1) * KD + k];
            const float a1y = sThL[(bg + 1) * KD + k];
            const float2 c0 = sC[k * 17 + vg];
            const float2 c1 = sC[k * 17 + vg + 1];
            rp00 = fmaf(a0x, c0.x, rp00); ab00 = fmaf(a0y, c0.x, fmaf(a0x, c0.y, ab00));
            rp01 = fmaf(a0x, c1.x, rp01); ab01 = fmaf(a0y, c1.x, fmaf(a0x, c1.y, ab01));
            rp10 = fmaf(a1x, c0.x, rp10); ab10 = fmaf(a1y, c0.x, fmaf(a1x, c0.y, ab10));
            rp11 = fmaf(a1x, c1.x, rp11); ab11 = fmaf(a1y, c1.x, fmaf(a1x, c1.y, ab11));
        }
        const int f0 = sFlag[vg], f1 = sFlag[vg + 1];
        #pragma unroll
        for (int e = 0; e < 4; e++) {
            const int i = e >> 1, j = e & 1;
            const float r  = (e==0)?rp00:(e==1)?rp01:(e==2)?rp10:rp11;
            const float a  = (e==0)?ab00:(e==1)?ab01:(e==2)?ab10:ab11;
            const int b = bg + i, vl = vg + j;
            float w = 0.0f;
            if (((j == 0) ? f0 : f1) == 0) {
                const float cnt = BOW[b * VD + v0 + vl];
                const float rpm = r + MINI_F;
                const float inv = __fdividef(1.0f, rpm);
                w = cnt * inv;
                if (cnt > 0.0f)
                    qz += a * inv - fast_log(rpm) * (r * inv);
            }
            sW[b * 17 + vl] = w;
        }
    }
    __syncthreads();

    // ---- GEMM2: EN[v,k] = crr * sum_b W[b,v]*theta[b,k]; ES zeros ----
    {
        const int vl = tid & 15;
        const int kg = (tid >> 4) * 4;
        float e0=0,e1=0,e2=0,e3=0;
        #pragma unroll 4
        for (int b = 0; b < BD; b++) {
            const float w = sW[b * 17 + vl];
            const float4 t4 = *reinterpret_cast<const float4*>(&sTh[b * KD + kg]);
            e0 = fmaf(w, t4.x, e0); e1 = fmaf(w, t4.y, e1);
            e2 = fmaf(w, t4.z, e2); e3 = fmaf(w, t4.w, e3);
        }
        const float4 c4 = *reinterpret_cast<const float4*>(&sC1T[vl * 68 + kg]);
        float4 o;
        o.x = e0 * c4.x; o.y = e1 * c4.y; o.z = e2 * c4.z; o.w = e3 * c4.w;
        const int gv = v0 + vl;
        *reinterpret_cast<float4*>(&out[OFF_N + gv * KD + kg]) = o;
        *reinterpret_cast<float4*>(&out[OFF_S + gv * KD + kg]) = make_float4(0.f, 0.f, 0.f, 0.f);
    }

    // ---- GEMM3: P[b,k] = sum_v W[b,v]*crr[v,k] ----
    {
        const int kg  = (tid & 15) * 4;
        const int bg3 = (tid >> 4) * 4;
        float p[4][4] = {};
        #pragma unroll 4
        for (int vl = 0; vl < VCH; vl++) {
            const float4 c4 = *reinterpret_cast<const float4*>(&sC1T[vl * 68 + kg]);
            const float w0 = sW[(bg3 + 0) * 17 + vl];
            const float w1 = sW[(bg3 + 1) * 17 + vl];
            const float w2 = sW[(bg3 + 2) * 17 + vl];
            const float w3 = sW[(bg3 + 3) * 17 + vl];
            p[0][0]=fmaf(w0,c4.x,p[0][0]); p[0][1]=fmaf(w0,c4.y,p[0][1]); p[0][2]=fmaf(w0,c4.z,p[0][2]); p[0][3]=fmaf(w0,c4.w,p[0][3]);
            p[1][0]=fmaf(w1,c4.x,p[1][0]); p[1][1]=fmaf(w1,c4.y,p[1][1]); p[1][2]=fmaf(w1,c4.z,p[1][2]); p[1][3]=fmaf(w1,c4.w,p[1][3]);
            p[2][0]=fmaf(w2,c4.x,p[2][0]); p[2][1]=fmaf(w2,c4.y,p[2][1]); p[2][2]=fmaf(w2,c4.z,p[2][2]); p[2][3]=fmaf(w2,c4.w,p[2][3]);
            p[3][0]=fmaf(w3,c4.x,p[3][0]); p[3][1]=fmaf(w3,c4.y,p[3][1]); p[3][2]=fmaf(w3,c4.z,p[3][2]); p[3][3]=fmaf(w3,c4.w,p[3][3]);
        }
        float* dst = g_P + blockIdx.x * (BD * KD);
        #pragma unroll
        for (int i = 0; i < 4; i++)
            *reinterpret_cast<float4*>(&dst[(bg3 + i) * KD + kg]) =
                make_float4(p[i][0], p[i][1], p[i][2], p[i][3]);
    }

    // qz: warp -> shared -> one global atomic per block
    qz = warp_sum(qz);
    __syncthreads();
    if ((tid & 31) == 0 && qz != 0.0f) atomicAdd(sQz, qz);
    __syncthreads();
    if (tid == 0 && *sQz != 0.0f) atomicAdd(&out[OFF_QZ], *sQz);
}

// ---- exact path for the seed rows; 2 warps per row (b-halves) ----
__global__ __launch_bounds__(256) void seed_kernel(
    const float* __restrict__ BOW,
    const float* __restrict__ seeds,
    const float* __restrict__ exp_s,
    const float* __restrict__ exp_n,
    const float* __restrict__ pi,
    float* __restrict__ out)
{
    __shared__ float sTh[BD * KD];
    const int tid = threadIdx.x;
    for (int i = tid; i < BD * KD; i += 256) sTh[i] = g_TL[i].x;
    __syncthreads();

    const int lane = tid & 31, warp = tid >> 5;
    const int gw = blockIdx.x * 8 + warp;
    const int nwarp = gridDim.x * 8;
    const int k0 = lane, k1 = lane + 32;
    const float invS0 = g_invS[k0], invS1 = g_invS[k1];
    const float invN0 = g_invN[k0], invN1 = g_invN[k1];
    const float pi0 = pi[k0], pi1 = pi[k1];
    const float q0 = 1.0f - pi0, q1 = 1.0f - pi1;
    const int nseed = g_nseed;

    float accGsr0 = 0.0f, accGsr1 = 0.0f, accQz = 0.0f;

    for (int idx = gw; idx < 2 * nseed; idx += nwarp) {
        const int v = g_seedlist[idx >> 1];
        const int bbase = (idx & 1) * 32;
        const int base = v * KD;

        const float sd0 = seeds[base + k0], sd1 = seeds[base + k1];
        const float ps0 = (MU_F  + exp_s[base + k0]) * invS0;
        const float ps1 = (MU_F  + exp_s[base + k1]) * invS1;
        const float pn0 = (BETA_F + exp_n[base + k0]) * invN0;
        const float pn1 = (BETA_F + exp_n[base + k1]) * invN1;
        const float crr0 = (1.0f - sd0) * pn0, crr1 = (1.0f - sd1) * pn1;
        const float css0 = sd0 * ps0 * pi0, css1 = sd1 * ps1 * pi1;
        const float csr0 = sd0 * pn0 * q0,  csr1 = sd1 * pn1 * q1;

        const float cntA = BOW[(bbase + lane) * VD + v];

        float aN0 = 0.f, aN1 = 0.f, aS0 = 0.f, aS1 = 0.f;

        for (int bb = 0; bb < 32; bb++) {
            const float cnt = __shfl_sync(0xffffffffu, cntA, bb);
            if (cnt <= 0.0f) continue;
            const int b = bbase + bb;
            const float th0 = sTh[b * KD + k0];
            const float th1 = sTh[b * KD + k1];
            float gss0 = th0 * css0, gss1 = th1 * css1;
            float gsr0 = th0 * csr0, gsr1 = th1 * csr1;
            float grr0 = th0 * crr0, grr1 = th1 * crr1;
            float sp = gss0 + gsr0 + gss1 + gsr1;
            float rp = grr0 + grr1;
            #pragma unroll
            for (int o = 16; o; o >>= 1) {
                sp += __shfl_xor_sync(0xffffffffu, sp, o);
                rp += __shfl_xor_sync(0xffffffffu, rp, o);
            }
            const float invs = __fdividef(1.0f, sp + MINI_F);
            const float invr = __fdividef(1.0f, rp + MINI_F);
            gss0 *= invs; gss1 *= invs;
            gsr0 *= invs; gsr1 *= invs;
            grr0 *= invr; grr1 *= invr;
            const float gam0 = pi0 * gss0 + q0 * (gsr0 + grr0);
            const float gam1 = pi1 * gss1 + q1 * (gsr1 + grr1);
            aN0 += (gsr0 + grr0) * cnt; aN1 += (gsr1 + grr1) * cnt;
            aS0 += gss0 * cnt;          aS1 += gss1 * cnt;
            accGsr0 += gsr0;            accGsr1 += gsr1;
            accQz += gam0 * __logf(gam0 + MINI_F) + gam1 * __logf(gam1 + MINI_F);
            atomicAdd(&g_Mseed[b * KD + k0], gam0 * cnt);
            atomicAdd(&g_Mseed[b * KD + k1], gam1 * cnt);
        }
        // fused wrote zeros for flagged rows; combine two half-warps via atomics
        if (aN0 != 0.0f) atomicAdd(&out[OFF_N + base + k0], aN0);
        if (aN1 != 0.0f) atomicAdd(&out[OFF_N + base + k1], aN1);
        if (aS0 != 0.0f) atomicAdd(&out[OFF_S + base + k0], aS0);
        if (aS1 != 0.0f) atomicAdd(&out[OFF_S + base + k1], aS1);
    }

    if (accGsr0 != 0.0f) atomicAdd(&out[OFF_GSR + k0], accGsr0);
    if (accGsr1 != 0.0f) atomicAdd(&out[OFF_GSR + k1], accGsr1);
    accQz = warp_sum(accQz);
    if (lane == 0 && accQz != 0.0f) atomicAdd(&out[OFF_QZ], accQz);
}

// out[i] += theta[i] * sum over 25 P-slices (y of 25 chunks); y==0 adds Mseed.
// Also resets g_nseed for the next run (seedlist already consumed).
__global__ void finalize_kernel(float* __restrict__ out) {
    const int i = blockIdx.x * blockDim.x + threadIdx.x;   // 0..4095
    const int j0 = blockIdx.y * 25;
    float s = 0.0f;
    #pragma unroll 5
    for (int j = 0; j < 25; j++)
        s += g_P[(j0 + j) * (BD * KD) + i];
    float add = g_TL[i].x * s;
    if (blockIdx.y == 0) add += g_Mseed[i];
    atomicAdd(&out[i], add);
    if (i == 0 && blockIdx.y == 0) g_nseed = 0;
}

extern "C" void kernel_launch(void* const* d_in, const int* in_sizes, int n_in,
                              void* d_out, int out_size) {
    const float* BOW   = (const float*)d_in[0];
    const float* seeds = (const float*)d_in[1];
    const float* exp_m = (const float*)d_in[2];
    const float* exp_s = (const float*)d_in[3];
    const float* exp_n = (const float*)d_in[4];
    const float* pi    = (const float*)d_in[5];
    float* out = (float*)d_out;

    static int smem_set = 0;
    if (!smem_set) {
        cudaFuncSetAttribute(fused_kernel, cudaFuncAttributeMaxDynamicSharedMemorySize, SMEM_FUSED);
        smem_set = 1;
    }

    zeroflag_kernel<<<79, 256>>>(seeds, out);
    colsum_kernel<<<592, 256>>>(seeds, exp_s, exp_n);
    prep_kernel<<<16, 256>>>(exp_m);
    fused_kernel<<<NCH, 256, SMEM_FUSED>>>(BOW, seeds, exp_n, out);
    seed_kernel<<<160, 256>>>(BOW, seeds, exp_s, exp_n, pi, out);
    finalize_kernel<<<dim3(16, 25), 256>>>(out);
}

// round 14
// speedup vs baseline: 1.2086x; 1.0324x over previous
#include <cuda_runtime.h>

// MixEHR_Seed: B=64, V=10000, K=64 — GEMM-factorized, 3-launch version.
// out: temp_exp_m_batch [64,64], temp_exp_n [V,K], temp_exp_s [V,K], gamma_sr_sum [K], exp_q_z [1]

#define KD      64
#define BD      64
#define VD      10000
#define VCH     16
#define NCH     625           // VD / VCH
#define SEEDBLK 40
#define ETA_F   0.1f
#define BETA_F  0.05f
#define MU_F    0.05f
#define MINI_F  1e-6f

#define OFF_N   4096
#define OFF_S   644096
#define OFF_GSR 1284096
#define OFF_QZ  1284160

// g_colS/ES/EN and g_nseed are zero at module load and re-zeroed by finalize
// each run, so prep can atomicAdd into them without a same-kernel reset race.
__device__ float  g_colS[KD];
__device__ float  g_colES[KD];
__device__ float  g_colEN[KD];
__device__ float2 g_TL[BD * KD];        // (theta, theta*log theta)
__device__ float  g_P[NCH * BD * KD];   // per-block W@crr partials (10.24 MB)
__device__ float  g_Mseed[BD * KD];
__device__ int    g_nseed;
__device__ int    g_seedlist[VD];
__device__ int    g_flag[VD];

__device__ __forceinline__ float warp_sum(float x) {
    #pragma unroll
    for (int o = 16; o; o >>= 1)
        x += __shfl_xor_sync(0xffffffffu, x, o);
    return x;
}

// ln(x) for positive normal x, FMA-pipe only. |err| ~2e-6.
__device__ __forceinline__ float fast_log(float x) {
    int ix = __float_as_int(x);
    int e  = (ix - 0x3f330000) >> 23;
    float m = __int_as_float(ix - (e << 23));
    float f = m - 1.0f;
    float p = 0.09090909f;
    p = fmaf(p, f, -0.1f);
    p = fmaf(p, f,  0.11111111f);
    p = fmaf(p, f, -0.125f);
    p = fmaf(p, f,  0.14285714f);
    p = fmaf(p, f, -0.16666667f);
    p = fmaf(p, f,  0.2f);
    p = fmaf(p, f, -0.25f);
    p = fmaf(p, f,  0.33333333f);
    p = fmaf(p, f, -0.5f);
    p = fmaf(p, f,  1.0f);
    return fmaf((float)e, 0.69314718f, p * f);
}

// ---- Launch 1: zero + TL + flag/seedlist + colsum, one kernel, grid 592 ----
__global__ void prep_kernel(const float* __restrict__ seeds,
                            const float* __restrict__ exp_s,
                            const float* __restrict__ exp_n,
                            const float* __restrict__ exp_m,
                            float* __restrict__ out) {
    const int gid = blockIdx.x * blockDim.x + threadIdx.x;
    if (gid < BD * KD) {
        const float th = exp_m[gid] + ETA_F;
        g_TL[gid] = make_float2(th, th * __logf(th));
        out[gid] = 0.0f;
        g_Mseed[gid] = 0.0f;
    }
    if (gid < KD) out[OFF_GSR + gid] = 0.0f;
    if (gid == 0) out[OFF_QZ] = 0.0f;

    // flag: 2 threads per row (halves), combined by shfl (full-warp participation)
    const int row = gid >> 1, half = gid & 1;
    int f = 0;
    if (row < VD) {
        const float4* sr = reinterpret_cast<const float4*>(seeds + row * KD + half * 32);
        #pragma unroll
        for (int q = 0; q < 8; q++) {
            float4 s4 = sr[q];
            f |= (s4.x > 0.0f) | (s4.y > 0.0f) | (s4.z > 0.0f) | (s4.w > 0.0f);
        }
    }
    f |= __shfl_xor_sync(0xffffffffu, f, 1);
    if (row < VD && half == 0) {
        g_flag[row] = f;
        if (f) {
            int pos = atomicAdd(&g_nseed, 1);
            g_seedlist[pos] = row;
        }
    }

    // colsum (strided over all threads)
    const int stride = gridDim.x * blockDim.x;
    float a = 0.0f, b = 0.0f, c = 0.0f;
    for (int i = gid; i < VD * KD; i += stride) {
        a += seeds[i]; b += exp_s[i]; c += exp_n[i];
    }
    const int k = gid & (KD - 1);
    atomicAdd(&g_colS[k], a);
    atomicAdd(&g_colES[k], b);
    atomicAdd(&g_colEN[k], c);
}

// ---- Launch 2: mega kernel — fused GEMMs (blocks 0..624) + seed rows (625..664) ----
// smem layout (bytes), padded b-/v-major planes, stride 68 floats:
#define SO_TH   0              // float[64*68] 17408
#define SO_THL  17408          // float[64*68] 17408
#define SO_CR   34816          // float[16*68]  4352  (crr, v-major)
#define SO_CL   39168          // float[16*68]  4352  (crr*logcrr, v-major)
#define SO_W    43520          // float[64*17]  4352
#define SO_FLAG 47872          // int[16]         64
#define SO_INVN 47936          // float[64]      256
#define SO_QZ   48192          // float            4
#define SMEM_MEGA 48208

__global__ __launch_bounds__(256, 4) void mega_kernel(
    const float* __restrict__ BOW,
    const float* __restrict__ seeds,
    const float* __restrict__ exp_s,
    const float* __restrict__ exp_n,
    const float* __restrict__ pi,
    float* __restrict__ out)
{
    extern __shared__ char smem[];
    const int tid = threadIdx.x;
    const int lane = tid & 31, warp = tid >> 5;

    if (blockIdx.x < NCH) {
        // ================= FUSED PATH (non-seed rows) =================
        float* sTh   = reinterpret_cast<float*>(smem + SO_TH);
        float* sThL  = reinterpret_cast<float*>(smem + SO_THL);
        float* sCr   = reinterpret_cast<float*>(smem + SO_CR);
        float* sCl   = reinterpret_cast<float*>(smem + SO_CL);
        float* sW    = reinterpret_cast<float*>(smem + SO_W);
        int*   sFlag = reinterpret_cast<int*>(smem + SO_FLAG);
        float* sInvN = reinterpret_cast<float*>(smem + SO_INVN);
        float* sQz   = reinterpret_cast<float*>(smem + SO_QZ);

        const int v0 = blockIdx.x * VCH;

        for (int i = tid; i < BD * KD; i += 256) {
            const int b = i >> 6, k = i & 63;
            const float2 tl = g_TL[i];
            sTh[b * 68 + k] = tl.x;
            sThL[b * 68 + k] = tl.y;
        }
        if (tid < KD) sInvN[tid] = __fdividef(1.0f, BETA_F * (float)VD + g_colEN[tid]);
        if (tid < VCH) sFlag[tid] = g_flag[v0 + tid];
        if (tid == 0) *sQz = 0.0f;
        __syncthreads();

        // crr / crr*logcrr (v-major, stride 68)
        #pragma unroll
        for (int r = 0; r < 4; r++) {
            const int i = tid + r * 256;        // 0..1023
            const int vl = i >> 6, k = i & 63;
            const float sd = seeds[(v0 + vl) * KD + k];
            const float en = exp_n[(v0 + vl) * KD + k];
            const float c1 = (1.0f - sd) * (BETA_F + en) * sInvN[k];
            sCr[vl * 68 + k] = c1;
            sCl[vl * 68 + k] = c1 * fast_log(c1 + 1e-30f);
        }
        __syncthreads();

        // ---- GEMM1: rp/ab over k (float4-vectorized); elementwise -> W, qz ----
        float qz = 0.0f;
        {
            const int tx = tid & 7,  ty = tid >> 3;
            const int vg = tx * 2,   bg = ty * 2;
            const int koff = tid & 4;              // stagger: de-conflict tx groups
            float rp00=0,rp01=0,rp10=0,rp11=0;
            float ab00=0,ab01=0,ab10=0,ab11=0;
            #pragma unroll 4
            for (int kq = 0; kq < KD; kq += 4) {
                const int k2 = (kq + koff) & 63;
                const float4 a0 = *reinterpret_cast<const float4*>(&sTh [bg * 68 + k2]);
                const float4 a1 = *reinterpret_cast<const float4*>(&sTh [(bg + 1) * 68 + k2]);
                const float4 l0 = *reinterpret_cast<const float4*>(&sThL[bg * 68 + k2]);
                const float4 l1 = *reinterpret_cast<const float4*>(&sThL[(bg + 1) * 68 + k2]);
                const float4 c0 = *reinterpret_cast<const float4*>(&sCr [vg * 68 + k2]);
                const float4 c1 = *reinterpret_cast<const float4*>(&sCr [(vg + 1) * 68 + k2]);
                const float4 d0 = *reinterpret_cast<const float4*>(&sCl [vg * 68 + k2]);
                const float4 d1 = *reinterpret_cast<const float4*>(&sCl [(vg + 1) * 68 + k2]);
                rp00 = fmaf(a0.x,c0.x,fmaf(a0.y,c0.y,fmaf(a0.z,c0.z,fmaf(a0.w,c0.w,rp00))));
                rp01 = fmaf(a0.x,c1.x,fmaf(a0.y,c1.y,fmaf(a0.z,c1.z,fmaf(a0.w,c1.w,rp01))));
                rp10 = fmaf(a1.x,c0.x,fmaf(a1.y,c0.y,fmaf(a1.z,c0.z,fmaf(a1.w,c0.w,rp10))));
                rp11 = fmaf(a1.x,c1.x,fmaf(a1.y,c1.y,fmaf(a1.z,c1.z,fmaf(a1.w,c1.w,rp11))));
                ab00 = fmaf(l0.x,c0.x,fmaf(l0.y,c0.y,fmaf(l0.z,c0.z,fmaf(l0.w,c0.w,ab00))));
                ab00 = fmaf(a0.x,d0.x,fmaf(a0.y,d0.y,fmaf(a0.z,d0.z,fmaf(a0.w,d0.w,ab00))));
                ab01 = fmaf(l0.x,c1.x,fmaf(l0.y,c1.y,fmaf(l0.z,c1.z,fmaf(l0.w,c1.w,ab01))));
                ab01 = fmaf(a0.x,d1.x,fmaf(a0.y,d1.y,fmaf(a0.z,d1.z,fmaf(a0.w,d1.w,ab01))));
                ab10 = fmaf(l1.x,c0.x,fmaf(l1.y,c0.y,fmaf(l1.z,c0.z,fmaf(l1.w,c0.w,ab10))));
                ab10 = fmaf(a1.x,d0.x,fmaf(a1.y,d0.y,fmaf(a1.z,d0.z,fmaf(a1.w,d0.w,ab10))));
                ab11 = fmaf(l1.x,c1.x,fmaf(l1.y,c1.y,fmaf(l1.z,c1.z,fmaf(l1.w,c1.w,ab11))));
                ab11 = fmaf(a1.x,d1.x,fmaf(a1.y,d1.y,fmaf(a1.z,d1.z,fmaf(a1.w,d1.w,ab11))));
            }
            const int f0 = sFlag[vg], f1 = sFlag[vg + 1];
            #pragma unroll
            for (int e = 0; e < 4; e++) {
                const int i = e >> 1, j = e & 1;
                const float r = (e==0)?rp00:(e==1)?rp01:(e==2)?rp10:rp11;
                const float a = (e==0)?ab00:(e==1)?ab01:(e==2)?ab10:ab11;
                const int b = bg + i, vl = vg + j;
                float w = 0.0f;
                if (((j == 0) ? f0 : f1) == 0) {
                    const float cnt = BOW[b * VD + v0 + vl];
                    const float rpm = r + MINI_F;
                    const float inv = __fdividef(1.0f, rpm);
                    w = cnt * inv;
                    if (cnt > 0.0f)
                        qz += a * inv - fast_log(rpm) * (r * inv);
                }
                sW[b * 17 + vl] = w;
            }
        }
        __syncthreads();

        // ---- GEMM2: EN[v,k] = crr * sum_b W[b,v]*theta[b,k]; skip flagged rows ----
        {
            const int vl = tid & 15;
            const int kg = (tid >> 4) * 4;
            float e0=0,e1=0,e2=0,e3=0;
            #pragma unroll 4
            for (int b = 0; b < BD; b++) {
                const float w = sW[b * 17 + vl];
                const float4 t4 = *reinterpret_cast<const float4*>(&sTh[b * 68 + kg]);
                e0 = fmaf(w, t4.x, e0); e1 = fmaf(w, t4.y, e1);
                e2 = fmaf(w, t4.z, e2); e3 = fmaf(w, t4.w, e3);
            }
            if (sFlag[vl] == 0) {
                const float4 c4 = *reinterpret_cast<const float4*>(&sCr[vl * 68 + kg]);
                float4 o;
                o.x = e0 * c4.x; o.y = e1 * c4.y; o.z = e2 * c4.z; o.w = e3 * c4.w;
                const int gv = v0 + vl;
                *reinterpret_cast<float4*>(&out[OFF_N + gv * KD + kg]) = o;
                *reinterpret_cast<float4*>(&out[OFF_S + gv * KD + kg]) = make_float4(0.f,0.f,0.f,0.f);
            }
        }

        // ---- GEMM3: P[b,k] = sum_v W[b,v]*crr[v,k] ----
        {
            const int kg  = (tid & 15) * 4;
            const int bg3 = (tid >> 4) * 4;
            float p[4][4] = {};
            #pragma unroll 4
            for (int vl = 0; vl < VCH; vl++) {
                const float4 c4 = *reinterpret_cast<const float4*>(&sCr[vl * 68 + kg]);
                const float w0 = sW[(bg3 + 0) * 17 + vl];
                const float w1 = sW[(bg3 + 1) * 17 + vl];
                const float w2 = sW[(bg3 + 2) * 17 + vl];
                const float w3 = sW[(bg3 + 3) * 17 + vl];
                p[0][0]=fmaf(w0,c4.x,p[0][0]); p[0][1]=fmaf(w0,c4.y,p[0][1]); p[0][2]=fmaf(w0,c4.z,p[0][2]); p[0][3]=fmaf(w0,c4.w,p[0][3]);
                p[1][0]=fmaf(w1,c4.x,p[1][0]); p[1][1]=fmaf(w1,c4.y,p[1][1]); p[1][2]=fmaf(w1,c4.z,p[1][2]); p[1][3]=fmaf(w1,c4.w,p[1][3]);
                p[2][0]=fmaf(w2,c4.x,p[2][0]); p[2][1]=fmaf(w2,c4.y,p[2][1]); p[2][2]=fmaf(w2,c4.z,p[2][2]); p[2][3]=fmaf(w2,c4.w,p[2][3]);
                p[3][0]=fmaf(w3,c4.x,p[3][0]); p[3][1]=fmaf(w3,c4.y,p[3][1]); p[3][2]=fmaf(w3,c4.z,p[3][2]); p[3][3]=fmaf(w3,c4.w,p[3][3]);
            }
            float* dst = g_P + blockIdx.x * (BD * KD);
            #pragma unroll
            for (int i = 0; i < 4; i++)
                *reinterpret_cast<float4*>(&dst[(bg3 + i) * KD + kg]) =
                    make_float4(p[i][0], p[i][1], p[i][2], p[i][3]);
        }

        // qz: warp -> shared -> one global atomic per block
        qz = warp_sum(qz);
        __syncthreads();
        if (lane == 0 && qz != 0.0f) atomicAdd(sQz, qz);
        __syncthreads();
        if (tid == 0 && *sQz != 0.0f) atomicAdd(&out[OFF_QZ], *sQz);

    } else {
        // ================= SEED PATH (one warp per row, exact) =================
        float* sTh64 = reinterpret_cast<float*>(smem);    // [64*64]
        for (int i = tid; i < BD * KD; i += 256) sTh64[i] = g_TL[i].x;
        __syncthreads();

        const int gw = (blockIdx.x - NCH) * 8 + warp;
        const int nwarp = SEEDBLK * 8;
        const int k0 = lane, k1 = lane + 32;
        const float invS0 = __fdividef(1.0f, MU_F * g_colS[k0] + g_colES[k0]);
        const float invS1 = __fdividef(1.0f, MU_F * g_colS[k1] + g_colES[k1]);
        const float invN0 = __fdividef(1.0f, BETA_F * (float)VD + g_colEN[k0]);
        const float invN1 = __fdividef(1.0f, BETA_F * (float)VD + g_colEN[k1]);
        const float pi0 = pi[k0], pi1 = pi[k1];
        const float q0 = 1.0f - pi0, q1 = 1.0f - pi1;
        const int nseed = g_nseed;

        float accGsr0 = 0.0f, accGsr1 = 0.0f, accQz = 0.0f;

        for (int idx = gw; idx < nseed; idx += nwarp) {
            const int v = g_seedlist[idx];
            const int base = v * KD;

            const float sd0 = seeds[base + k0], sd1 = seeds[base + k1];
            const float ps0 = (MU_F  + exp_s[base + k0]) * invS0;
            const float ps1 = (MU_F  + exp_s[base + k1]) * invS1;
            const float pn0 = (BETA_F + exp_n[base + k0]) * invN0;
            const float pn1 = (BETA_F + exp_n[base + k1]) * invN1;
            const float crr0 = (1.0f - sd0) * pn0, crr1 = (1.0f - sd1) * pn1;
            const float css0 = sd0 * ps0 * pi0, css1 = sd1 * ps1 * pi1;
            const float csr0 = sd0 * pn0 * q0,  csr1 = sd1 * pn1 * q1;

            const float cntA = BOW[lane * VD + v];
            const float cntB = BOW[(lane + 32) * VD + v];

            float aN0 = 0.f, aN1 = 0.f, aS0 = 0.f, aS1 = 0.f;

            for (int b = 0; b < BD; b++) {
                const float cnt = __shfl_sync(0xffffffffu, (b < 32) ? cntA : cntB, b & 31);
                if (cnt <= 0.0f) continue;
                const float th0 = sTh64[b * KD + k0];
                const float th1 = sTh64[b * KD + k1];
                float gss0 = th0 * css0, gss1 = th1 * css1;
                float gsr0 = th0 * csr0, gsr1 = th1 * csr1;
                float grr0 = th0 * crr0, grr1 = th1 * crr1;
                float sp = gss0 + gsr0 + gss1 + gsr1;
                float rp = grr0 + grr1;
                #pragma unroll
                for (int o = 16; o; o >>= 1) {
                    sp += __shfl_xor_sync(0xffffffffu, sp, o);
                    rp += __shfl_xor_sync(0xffffffffu, rp, o);
                }
                const float invs = __fdividef(1.0f, sp + MINI_F);
                const float invr = __fdividef(1.0f, rp + MINI_F);
                gss0 *= invs; gss1 *= invs;
                gsr0 *= invs; gsr1 *= invs;
                grr0 *= invr; grr1 *= invr;
                const float gam0 = pi0 * gss0 + q0 * (gsr0 + grr0);
                const float gam1 = pi1 * gss1 + q1 * (gsr1 + grr1);
                aN0 += (gsr0 + grr0) * cnt; aN1 += (gsr1 + grr1) * cnt;
                aS0 += gss0 * cnt;          aS1 += gss1 * cnt;
                accGsr0 += gsr0;            accGsr1 += gsr1;
                accQz += gam0 * __logf(gam0 + MINI_F) + gam1 * __logf(gam1 + MINI_F);
                atomicAdd(&g_Mseed[b * KD + k0], gam0 * cnt);
                atomicAdd(&g_Mseed[b * KD + k1], gam1 * cnt);
            }
            // whole row owned by this warp -> plain stores (fused skipped flagged rows)
            out[OFF_N + base + k0] = aN0; out[OFF_N + base + k1] = aN1;
            out[OFF_S + base + k0] = aS0; out[OFF_S + base + k1] = aS1;
        }

        if (accGsr0 != 0.0f) atomicAdd(&out[OFF_GSR + k0], accGsr0);
        if (accGsr1 != 0.0f) atomicAdd(&out[OFF_GSR + k1], accGsr1);
        accQz = warp_sum(accQz);
        if (lane == 0 && accQz != 0.0f) atomicAdd(&out[OFF_QZ], accQz);
    }
}

// ---- Launch 3: finalize exp_m; reset persistent accumulators for next run ----
__global__ void finalize_kernel(float* __restrict__ out) {
    const int i = blockIdx.x * blockDim.x + threadIdx.x;   // 0..4095
    const int j0 = blockIdx.y * 25;
    float s = 0.0f;
    #pragma unroll 5
    for (int j = 0; j < 25; j++)
        s += g_P[(j0 + j) * (BD * KD) + i];
    float add = g_TL[i].x * s;
    if (blockIdx.y == 0) add += g_Mseed[i];
    atomicAdd(&out[i], add);
    if (blockIdx.y == 0) {
        if (i < KD) { g_colS[i] = 0.0f; g_colES[i] = 0.0f; g_colEN[i] = 0.0f; }
        if (i == 0) g_nseed = 0;
    }
}

extern "C" void kernel_launch(void* const* d_in, const int* in_sizes, int n_in,
                              void* d_out, int out_size) {
    const float* BOW   = (const float*)d_in[0];
    const float* seeds = (const float*)d_in[1];
    const float* exp_m = (const float*)d_in[2];
    const float* exp_s = (const float*)d_in[3];
    const float* exp_n = (const float*)d_in[4];
    const float* pi    = (const float*)d_in[5];
    float* out = (float*)d_out;

    prep_kernel<<<592, 256>>>(seeds, exp_s, exp_n, exp_m, out);
    mega_kernel<<<NCH + SEEDBLK, 256, SMEM_MEGA>>>(BOW, seeds, exp_s, exp_n, pi, out);
    finalize_kernel<<<dim3(16, 25), 256>>>(out);
}